// round 12
// baseline (speedup 1.0000x reference)
#include <cuda_runtime.h>
#include <stdint.h>

#define BB 64
#define TT 256
#define NN 64
#define XPAD 68                  // padded xs row stride (floats)
#define BPAD 68                  // padded bits row stride (u32)
#define NTHR 544                 // 17 warps: 512 pack threads + exact Gram fit
#define NSL 4                    // accumulator slices (t & 3) to break RED bursts

__device__ int g_part[NSL][NN * NN];   // sliced Hamming accumulators (i<j)

// ---------------- zero the sliced accumulators (PDL-chainable kernel) --------
__global__ __launch_bounds__(128) void zeroK() {
    ((int4*)g_part)[blockIdx.x * 128 + threadIdx.x] = make_int4(0, 0, 0, 0);
}

// ---------------- fused: shuffle bit-pack + XOR/popcount Gram, one block per t
// Word layout per column (64 words, identical mapping for every column):
//  word a      (a=0..31): bit w = [x[a] > x[32+w]]                  (1024 pairs)
//  word 32+a   (a=0..31): bit s-1  = [x[a] > x[(a+s)&31]], s=1..16  (lo half)
//                         bit 15+s = [x[32+a] > x[32+((a+s)&31)]]   (hi half)
//              lanes >= 16 mask bits 15,31 (s=16 duplicate pairs) -> 992 pairs
__global__ __launch_bounds__(NTHR) void fusedKD(const float4* __restrict__ in4) {
    __shared__ __align__(16) float    xs[BB][XPAD];    // 17.4 KB staged slab
    __shared__ __align__(16) uint32_t bits[64][BPAD];  // 17.4 KB bit matrix
    __shared__ uint32_t lut[136];                      // tile -> (i0<<8)|j0
    const int tid  = threadIdx.x;
    const int t    = blockIdx.x;
    const int lane = tid & 31, warp = tid >> 5;

    // Coalesced staging of the 64x64 slab (1024 float4). Reads only the input,
    // so this overlaps the zeroK dependency under PDL.
    for (int q = tid; q < BB * 16; q += NTHR) {
        int b = q >> 4, c = q & 15;
        *(float4*)&xs[b][c * 4] = in4[(size_t)b * (TT * 16) + (size_t)t * 16 + c];
    }
    // Tile LUT: 136 upper-triangle 4x4 tiles.
    if (tid < 136) {
        int ti = 0, rem = tid;
        while (rem >= 16 - ti) { rem -= 16 - ti; ti++; }
        int tj = ti + rem;
        lut[tid] = (uint32_t)((ti << 2) << 8) | (uint32_t)(tj << 2);
    }
    __syncthreads();

    // Shuffle bit-pack: warps 0..15, warp = col-group (4 cols), lane = batch a.
    if (tid < 512) {
        float4 flo = *(const float4*)&xs[lane][warp * 4];
        float4 fhi = *(const float4*)&xs[lane + 32][warp * 4];
        float xl[4] = {flo.x, flo.y, flo.z, flo.w};
        float xh[4] = {fhi.x, fhi.y, fhi.z, fhi.w};

        #pragma unroll
        for (int k = 0; k < 4; k++) {
            uint32_t wA = 0u, wB = 0u;
            #pragma unroll
            for (int w = 0; w < 32; w++) {
                float xb = __shfl_sync(0xFFFFFFFFu, xh[k], w);
                if (xl[k] > xb) wA |= (1u << w);
            }
            #pragma unroll
            for (int s = 1; s <= 16; s++) {
                float rl = __shfl_sync(0xFFFFFFFFu, xl[k], lane + s);  // mod 32
                float rh = __shfl_sync(0xFFFFFFFFu, xh[k], lane + s);
                if (xl[k] > rl) wB |= (1u << (s - 1));
                if (xh[k] > rh) wB |= (1u << (15 + s));
            }
            if (lane >= 16) wB &= 0x7FFF7FFFu;   // kill s=16 duplicate pairs
            int col = (warp << 2) + k;
            bits[lane][col]      = wA;
            bits[32 + lane][col] = wB;
        }
    }
    __syncthreads();

    // Gram: 136 tiles x 4 interleaved word-sets = 544 tasks, one per thread.
    // Quad lanes read rows w..w+3 (disjoint bank spans); same-(row,col) loads
    // across quads are identical addresses (broadcast) -> conflict-free.
    {
        uint32_t ij = lut[tid >> 2];
        int i0 = (int)(ij >> 8), j0 = (int)(ij & 255);
        int r = tid & 3;

        int acc[16];
        #pragma unroll
        for (int k = 0; k < 16; k++) acc[k] = 0;
        #pragma unroll
        for (int step = 0; step < 16; step++) {
            int w = r + (step << 2);
            uint4 bi = *(const uint4*)&bits[w][i0];
            uint4 bj = *(const uint4*)&bits[w][j0];
            uint32_t iv[4] = {bi.x, bi.y, bi.z, bi.w};
            uint32_t jv[4] = {bj.x, bj.y, bj.z, bj.w};
            #pragma unroll
            for (int ii = 0; ii < 4; ii++)
                #pragma unroll
                for (int jj = 0; jj < 4; jj++)
                    acc[ii * 4 + jj] += __popc(iv[ii] ^ jv[jj]);
        }
        #pragma unroll
        for (int k = 0; k < 16; k++) {
            acc[k] += __shfl_xor_sync(0xFFFFFFFFu, acc[k], 1);
            acc[k] += __shfl_xor_sync(0xFFFFFFFFu, acc[k], 2);
        }

        // First touch of zeroK's output: resolve the PDL dependency here, after
        // all heavy work has already overlapped with the predecessor.
        cudaGridDependencySynchronize();

        if (r == 0) {
            int* Hsl = g_part[t & (NSL - 1)];
            #pragma unroll
            for (int k = 0; k < 16; k++) {
                int i = i0 + (k >> 2), j = j0 + (k & 3);
                if (i < j) atomicAdd(&Hsl[i * NN + j], acc[k]);  // fire-and-forget
            }
        }
    }
}

// ---------------- distance + broadcast: 256 blocks, one (copy, quarter) each --
// D[i,j] = 1 - (1032192 - 4H)/2016 (2K - 4H with K = 516096), diag 0.
__global__ __launch_bounds__(256) void phase3(float* __restrict__ out) {
    __shared__ __align__(16) int Hs[NN * NN];   // 16 KB
    int tid = threadIdx.x;
    int cp = blockIdx.x >> 2, q = blockIdx.x & 3;

    cudaGridDependencySynchronize();            // wait for fusedKD's REDs

    {
        const int4* s0 = (const int4*)g_part[0];
        const int4* s1 = (const int4*)g_part[1];
        const int4* s2 = (const int4*)g_part[2];
        const int4* s3 = (const int4*)g_part[3];
        int4* d = (int4*)Hs;
        for (int k = tid; k < 1024; k += 256) {
            int4 a = __ldg(&s0[k]), b = __ldg(&s1[k]);
            int4 c = __ldg(&s2[k]), e = __ldg(&s3[k]);
            d[k] = make_int4(a.x + b.x + c.x + e.x, a.y + b.y + c.y + e.y,
                             a.z + b.z + c.z + e.z, a.w + b.w + c.w + e.w);
        }
    }
    __syncthreads();

    int base = (q << 10) + (tid << 2);          // 4 contiguous cells, same row
    int i = base >> 6, j0 = base & 63;
    float v[4];
    #pragma unroll
    for (int u = 0; u < 4; u++) {
        int j = j0 + u;
        float d = 0.0f;
        if (i != j) {
            int h = (i < j) ? Hs[i * NN + j] : Hs[j * NN + i];
            d = 1.0f - (1032192.0f - 4.0f * (float)h) * (1.0f / 2016.0f);
        }
        v[u] = d;
    }
    *(float4*)(out + (size_t)cp * (NN * NN) + base) = make_float4(v[0], v[1], v[2], v[3]);
}

extern "C" void kernel_launch(void* const* d_in, const int* in_sizes, int n_in,
                              void* d_out, int out_size) {
    (void)in_sizes; (void)n_in; (void)out_size;
    const float4* in4 = (const float4*)d_in[0];
    float* out = (float*)d_out;

    zeroK<<<NSL * NN * NN / 4 / 128, 128>>>();   // 4096 int4 -> 32 blocks

    cudaLaunchAttribute at[1];
    at[0].id = cudaLaunchAttributeProgrammaticStreamSerialization;
    at[0].val.programmaticStreamSerializationAllowed = 1;

    cudaLaunchConfig_t cfg = {};
    cfg.attrs = at; cfg.numAttrs = 1; cfg.stream = 0;

    cfg.gridDim = dim3(TT); cfg.blockDim = dim3(NTHR);
    if (cudaLaunchKernelEx(&cfg, fusedKD, in4) != cudaSuccess)
        fusedKD<<<TT, NTHR>>>(in4);              // fallback: gridsync is a no-op

    cfg.gridDim = dim3(TT); cfg.blockDim = dim3(256);
    if (cudaLaunchKernelEx(&cfg, phase3, out) != cudaSuccess)
        phase3<<<TT, 256>>>(out);
}

// round 13
// speedup vs baseline: 1.0077x; 1.0077x over previous
#include <cuda_runtime.h>
#include <stdint.h>

#define BB 64
#define TT 256
#define NN 64
#define XPAD 68                  // padded xs row stride (floats)
#define BPAD 68                  // padded bits row stride (u32)
#define NTHR 544                 // 17 warps: 512 pack threads + exact Gram fit

__device__ int   g_H[NN * NN];   // Hamming accumulators (i<j); reset by epilogue
__device__ float g_D[NN * NN];   // distance matrix, written by last block
__device__ int   g_cnt;          // monotone arrival counter (never reset)
__device__ volatile int g_flag;  // monotone generation flag

// ---------------- single fused kernel: pack + Gram + last-block epilogue ------
// Word layout per column (64 words, identical mapping for every column):
//  word a      (a=0..31): bit w = [x[a] > x[32+w]]                  (1024 pairs)
//  word 32+a   (a=0..31): bit s-1  = [x[a] > x[(a+s)&31]], s=1..16  (lo half)
//                         bit 15+s = [x[32+a] > x[32+((a+s)&31)]]   (hi half)
//              lanes >= 16 mask bits 15,31 (s=16 duplicate pairs) -> 992 pairs
// Orientation is identical across columns, so popc(word_i ^ word_j) counts
// discordant pairs exactly; masked bits contribute 0.
__global__ __launch_bounds__(NTHR, 2) void fusedKD(const float4* __restrict__ in4,
                                                   float* __restrict__ out) {
    __shared__ __align__(16) float    xs[BB][XPAD];    // 17.4 KB staged slab
    __shared__ __align__(16) uint32_t bits[64][BPAD];  // 17.4 KB bit matrix (reused as Hs)
    __shared__ uint32_t lut[136];                      // tile -> (i0<<8)|j0
    __shared__ int s_old;
    const int tid  = threadIdx.x;
    const int t    = blockIdx.x;
    const int lane = tid & 31, warp = tid >> 5;

    // Coalesced staging of the 64x64 slab (1024 float4).
    for (int q = tid; q < BB * 16; q += NTHR) {
        int b = q >> 4, c = q & 15;
        *(float4*)&xs[b][c * 4] = in4[(size_t)b * (TT * 16) + (size_t)t * 16 + c];
    }
    // Tile LUT: 136 upper-triangle 4x4 tiles.
    if (tid < 136) {
        int ti = 0, rem = tid;
        while (rem >= 16 - ti) { rem -= 16 - ti; ti++; }
        int tj = ti + rem;
        lut[tid] = (uint32_t)((ti << 2) << 8) | (uint32_t)(tj << 2);
    }
    __syncthreads();

    // Shuffle bit-pack: warps 0..15, warp = col-group (4 cols), lane = batch a.
    if (tid < 512) {
        float4 flo = *(const float4*)&xs[lane][warp * 4];
        float4 fhi = *(const float4*)&xs[lane + 32][warp * 4];
        float xl[4] = {flo.x, flo.y, flo.z, flo.w};
        float xh[4] = {fhi.x, fhi.y, fhi.z, fhi.w};

        #pragma unroll
        for (int k = 0; k < 4; k++) {
            uint32_t wA = 0u, wB = 0u;
            #pragma unroll
            for (int w = 0; w < 32; w++) {
                float xb = __shfl_sync(0xFFFFFFFFu, xh[k], w);
                if (xl[k] > xb) wA |= (1u << w);
            }
            #pragma unroll
            for (int s = 1; s <= 16; s++) {
                float rl = __shfl_sync(0xFFFFFFFFu, xl[k], lane + s);  // mod 32
                float rh = __shfl_sync(0xFFFFFFFFu, xh[k], lane + s);
                if (xl[k] > rl) wB |= (1u << (s - 1));
                if (xh[k] > rh) wB |= (1u << (15 + s));
            }
            if (lane >= 16) wB &= 0x7FFF7FFFu;   // kill s=16 duplicate pairs
            int col = (warp << 2) + k;
            bits[lane][col]      = wA;
            bits[32 + lane][col] = wB;
        }
    }
    __syncthreads();

    // Gram: 136 tiles x 4 interleaved word-sets = 544 tasks, one per thread.
    // Quad lanes read rows w..w+3 (disjoint bank spans); same-(row,col) loads
    // across quads broadcast -> conflict-free crossbar traffic.
    {
        uint32_t ij = lut[tid >> 2];
        int i0 = (int)(ij >> 8), j0 = (int)(ij & 255);
        int r = tid & 3;

        int acc[16];
        #pragma unroll
        for (int k = 0; k < 16; k++) acc[k] = 0;
        #pragma unroll
        for (int step = 0; step < 16; step++) {
            int w = r + (step << 2);
            uint4 bi = *(const uint4*)&bits[w][i0];
            uint4 bj = *(const uint4*)&bits[w][j0];
            uint32_t iv[4] = {bi.x, bi.y, bi.z, bi.w};
            uint32_t jv[4] = {bj.x, bj.y, bj.z, bj.w};
            #pragma unroll
            for (int ii = 0; ii < 4; ii++)
                #pragma unroll
                for (int jj = 0; jj < 4; jj++)
                    acc[ii * 4 + jj] += __popc(iv[ii] ^ jv[jj]);
        }
        #pragma unroll
        for (int k = 0; k < 16; k++) {
            acc[k] += __shfl_xor_sync(0xFFFFFFFFu, acc[k], 1);
            acc[k] += __shfl_xor_sync(0xFFFFFFFFu, acc[k], 2);
        }
        if (r == 0) {
            #pragma unroll
            for (int k = 0; k < 16; k++) {
                int i = i0 + (k >> 2), j = j0 + (k & 3);
                if (i < j) atomicAdd(&g_H[i * NN + j], acc[k]);  // fire-and-forget
            }
        }
    }
    __syncthreads();

    // ---- arrival: detect the last block of this replay ----
    if (tid == 0) {
        __threadfence();                         // make our REDs visible first
        s_old = atomicAdd(&g_cnt, 1);
    }
    __syncthreads();
    const int old = s_old;
    const int gen = (old >> 8) + 1;              // generation = replay index + 1

    if ((old & 255) == 255) {
        // ---- last block: H -> D, reset H for next replay, publish flag ----
        int* Hs = (int*)bits;                    // reuse smem
        {
            const int4* s = (const int4*)g_H;
            int4* d4 = (int4*)Hs;
            for (int k = tid; k < 1024; k += NTHR) d4[k] = __ldcg(&s[k]);
        }
        __syncthreads();
        for (int k = tid; k < NN * NN; k += NTHR) {
            int i = k >> 6, j = k & 63;
            float dv = 0.0f;
            if (i != j) {
                int h = (i < j) ? Hs[i * NN + j] : Hs[j * NN + i];
                dv = 1.0f - (1032192.0f - 4.0f * (float)h) * (1.0f / 2016.0f);
            }
            g_D[k] = dv;
        }
        for (int k = tid; k < 1024; k += NTHR)   // self-clean for next replay
            ((int4*)g_H)[k] = make_int4(0, 0, 0, 0);
        __threadfence();
        __syncthreads();
        if (tid == 0) g_flag = gen;              // release
    }

    // ---- all blocks: wait for D, then copy own 4 KB slice of the broadcast ----
    if (tid == 0) {
        while (g_flag < gen) __nanosleep(64);
        __threadfence();                         // acquire
    }
    __syncthreads();
    {
        int cp = blockIdx.x >> 2, q = blockIdx.x & 3;
        const float4* s = (const float4*)g_D + (q << 8);
        float4* o = (float4*)(out + (size_t)cp * (NN * NN)) + (q << 8);
        if (tid < 256) o[tid] = s[tid];
    }
}

extern "C" void kernel_launch(void* const* d_in, const int* in_sizes, int n_in,
                              void* d_out, int out_size) {
    (void)in_sizes; (void)n_in; (void)out_size;
    const float4* in4 = (const float4*)d_in[0];
    float* out = (float*)d_out;

    fusedKD<<<TT, NTHR>>>(in4, out);
}

// round 14
// speedup vs baseline: 1.1604x; 1.1515x over previous
#include <cuda_runtime.h>
#include <stdint.h>

#define BB 64
#define TT 256
#define NN 64
#define BPAD 68                  // padded bits row stride (u32)
#define NTHR 544                 // 17 warps: 512 pack threads + exact Gram fit

__device__ int g_H[NN * NN];     // Hamming accumulators (i<j); self-cleaned by phase3

// ---------------- fused: shuffle bit-pack + XOR/popcount Gram, one block per t
// Word layout per column (64 words, identical mapping for every column):
//  word a      (a=0..31): bit w = [x[a] > x[32+w]]                  (1024 pairs)
//  word 32+a   (a=0..31): bit s-1  = [x[a] > x[(a+s)&31]], s=1..16  (lo half)
//                         bit 15+s = [x[32+a] > x[32+((a+s)&31)]]   (hi half)
//              lanes >= 16 mask bits 15,31 (s=16 duplicate pairs) -> 992 pairs
// Orientation is identical across columns, so popc(word_i ^ word_j) counts
// discordant pairs exactly; masked bits contribute 0.
__global__ __launch_bounds__(NTHR, 2) void fusedKD(const float4* __restrict__ in4) {
    __shared__ __align__(16) uint32_t bits[64][BPAD];  // 17.4 KB bit matrix
    __shared__ uint32_t lut[136];                      // tile -> (i0<<8)|j0
    const int tid  = threadIdx.x;
    const int t    = blockIdx.x;
    const int lane = tid & 31, warp = tid >> 5;

    // Tile LUT: 136 upper-triangle 4x4 tiles.
    if (tid < 136) {
        int ti = 0, rem = tid;
        while (rem >= 16 - ti) { rem -= 16 - ti; ti++; }
        int tj = ti + rem;
        lut[tid] = (uint32_t)((ti << 2) << 8) | (uint32_t)(tj << 2);
    }

    // Shuffle bit-pack: warps 0..15, warp = col-group (4 cols), lane = batch a.
    // Direct L2-resident loads (4 MB input): lane a reads x[a][t][4w..4w+3].
    if (tid < 512) {
        float4 flo = __ldg(&in4[(size_t)lane * (TT * 16) + (size_t)t * 16 + warp]);
        float4 fhi = __ldg(&in4[(size_t)(lane + 32) * (TT * 16) + (size_t)t * 16 + warp]);
        float xl[4] = {flo.x, flo.y, flo.z, flo.w};
        float xh[4] = {fhi.x, fhi.y, fhi.z, fhi.w};

        #pragma unroll
        for (int k = 0; k < 4; k++) {
            uint32_t wA = 0u, wB = 0u;
            #pragma unroll
            for (int w = 0; w < 32; w++) {
                float xb = __shfl_sync(0xFFFFFFFFu, xh[k], w);
                if (xl[k] > xb) wA |= (1u << w);
            }
            #pragma unroll
            for (int s = 1; s <= 16; s++) {
                float rl = __shfl_sync(0xFFFFFFFFu, xl[k], lane + s);  // mod 32
                float rh = __shfl_sync(0xFFFFFFFFu, xh[k], lane + s);
                if (xl[k] > rl) wB |= (1u << (s - 1));
                if (xh[k] > rh) wB |= (1u << (15 + s));
            }
            if (lane >= 16) wB &= 0x7FFF7FFFu;   // kill s=16 duplicate pairs
            int col = (warp << 2) + k;
            bits[lane][col]      = wA;
            bits[32 + lane][col] = wB;
        }
    }
    __syncthreads();

    // Gram: 136 tiles x 4 interleaved word-sets = 544 tasks, one per thread.
    // Quad lanes read rows w..w+3 (disjoint bank spans); same-(row,col) loads
    // across quads broadcast -> conflict-free crossbar traffic.
    {
        uint32_t ij = lut[tid >> 2];
        int i0 = (int)(ij >> 8), j0 = (int)(ij & 255);
        int r = tid & 3;

        int acc[16];
        #pragma unroll
        for (int k = 0; k < 16; k++) acc[k] = 0;
        #pragma unroll
        for (int step = 0; step < 16; step++) {
            int w = r + (step << 2);
            uint4 bi = *(const uint4*)&bits[w][i0];
            uint4 bj = *(const uint4*)&bits[w][j0];
            uint32_t iv[4] = {bi.x, bi.y, bi.z, bi.w};
            uint32_t jv[4] = {bj.x, bj.y, bj.z, bj.w};
            #pragma unroll
            for (int ii = 0; ii < 4; ii++)
                #pragma unroll
                for (int jj = 0; jj < 4; jj++)
                    acc[ii * 4 + jj] += __popc(iv[ii] ^ jv[jj]);
        }
        #pragma unroll
        for (int k = 0; k < 16; k++) {
            acc[k] += __shfl_xor_sync(0xFFFFFFFFu, acc[k], 1);
            acc[k] += __shfl_xor_sync(0xFFFFFFFFu, acc[k], 2);
        }
        if (r == 0) {
            #pragma unroll
            for (int k = 0; k < 16; k++) {
                int i = i0 + (k >> 2), j = j0 + (k & 3);
                if (i < j) atomicAdd(&g_H[i * NN + j], acc[k]);  // fire-and-forget
            }
        }
    }
}

// ---------------- distance + broadcast + self-clean ---------------------------
// D[i,j] = 1 - (1032192 - 4H)/2016 (2K - 4H with K = 516096), diag 0.
// After reading H, each block zeroes a distinct slice so the next graph replay
// starts from a clean accumulator (kernel-boundary ordering makes this exact).
__global__ __launch_bounds__(256) void phase3(float* __restrict__ out) {
    __shared__ __align__(16) int Hs[NN * NN];   // 16 KB
    int tid = threadIdx.x;
    int cp = blockIdx.x >> 2, q = blockIdx.x & 3;

    cudaGridDependencySynchronize();            // PDL: wait for fusedKD's REDs

    {
        const int4* s = (const int4*)g_H;
        int4* d = (int4*)Hs;
        for (int k = tid; k < 1024; k += 256) d[k] = __ldg(&s[k]);
    }
    __syncthreads();

    // Self-clean: block b zeroes int4 slice [4b, 4b+4) -> 256 blocks cover 4096 ints.
    if (tid < 4) ((int4*)g_H)[blockIdx.x * 4 + tid] = make_int4(0, 0, 0, 0);

    int base = (q << 10) + (tid << 2);          // 4 contiguous cells, same row
    int i = base >> 6, j0 = base & 63;
    float v[4];
    #pragma unroll
    for (int u = 0; u < 4; u++) {
        int j = j0 + u;
        float d = 0.0f;
        if (i != j) {
            int h = (i < j) ? Hs[i * NN + j] : Hs[j * NN + i];
            d = 1.0f - (1032192.0f - 4.0f * (float)h) * (1.0f / 2016.0f);
        }
        v[u] = d;
    }
    *(float4*)(out + (size_t)cp * (NN * NN) + base) = make_float4(v[0], v[1], v[2], v[3]);
}

extern "C" void kernel_launch(void* const* d_in, const int* in_sizes, int n_in,
                              void* d_out, int out_size) {
    (void)in_sizes; (void)n_in; (void)out_size;
    const float4* in4 = (const float4*)d_in[0];
    float* out = (float*)d_out;

    fusedKD<<<TT, NTHR>>>(in4);

    // phase3 with programmatic dependent launch (prologue overlaps fusedKD tail);
    // plain launch fallback if the attribute is rejected under capture.
    cudaLaunchAttribute at[1];
    at[0].id = cudaLaunchAttributeProgrammaticStreamSerialization;
    at[0].val.programmaticStreamSerializationAllowed = 1;
    cudaLaunchConfig_t cfg = {};
    cfg.gridDim = dim3(TT); cfg.blockDim = dim3(256);
    cfg.attrs = at; cfg.numAttrs = 1; cfg.stream = 0;
    if (cudaLaunchKernelEx(&cfg, phase3, out) != cudaSuccess)
        phase3<<<TT, 256>>>(out);
}

// round 15
// speedup vs baseline: 1.1692x; 1.0076x over previous
#include <cuda_runtime.h>
#include <stdint.h>

#define BB 64
#define TT 256
#define NN 64
#define BPAD 68                  // padded bits row stride (u32)
#define NTHR 544                 // 17 warps: 512 pack threads + exact Gram fit

__device__ int g_H[NN * NN];     // Hamming accumulators (i<j); self-cleaned by phase3

// ---------------- fused: rotation bit-pack + XOR/popcount Gram, one block per t
// Per column, 64 words; slot -> (pair, orientation) is identical across columns,
// so popc(word_i ^ word_j) counts discordant pairs exactly.
//  word C = bits[lane]    : bit 0     = [x[a] > x[32+a]]                  (d=0)
//                           bit s     = [x[a] > x[32+((a+s)&31)]], s=1..16 (cross1)
//                           bit 16+s  = [x[32+a] > x[(a+s)&31]],  s=1..15 (cross2,
//                                        = pair (a+s, 32+a) reversed — consistent)
//  word L = bits[32+lane] : bit s-1   = [x[a] > x[(a+s)&31]],    s=1..16  (lo half)
//                           bit 15+s  = [x[32+a] > x[32+((a+s)&31)]]      (hi half)
//                           lanes >= 16 mask bits 15,31 (s=16 duplicates)
// Coverage: 32(d0) + 512(cross1) + 480(cross2) + 992(lo+hi) = 2016 pairs, each once.
// Only 2 shuffles per rotation step serve 4 comparisons -> 32 shfl/col (was 64).
__global__ __launch_bounds__(NTHR, 2) void fusedKD(const float4* __restrict__ in4) {
    __shared__ __align__(16) uint32_t bits[64][BPAD];  // 17.4 KB bit matrix
    __shared__ uint32_t lut[136];                      // tile -> (i0<<8)|j0
    const int tid  = threadIdx.x;
    const int t    = blockIdx.x;
    const int lane = tid & 31, warp = tid >> 5;

    // Tile LUT: 136 upper-triangle 4x4 tiles.
    if (tid < 136) {
        int ti = 0, rem = tid;
        while (rem >= 16 - ti) { rem -= 16 - ti; ti++; }
        int tj = ti + rem;
        lut[tid] = (uint32_t)((ti << 2) << 8) | (uint32_t)(tj << 2);
    }

    // Rotation bit-pack: warps 0..15, warp = col-group (4 cols), lane = batch a.
    if (tid < 512) {
        float4 flo = __ldg(&in4[(size_t)lane * (TT * 16) + (size_t)t * 16 + warp]);
        float4 fhi = __ldg(&in4[(size_t)(lane + 32) * (TT * 16) + (size_t)t * 16 + warp]);
        float xl[4] = {flo.x, flo.y, flo.z, flo.w};
        float xh[4] = {fhi.x, fhi.y, fhi.z, fhi.w};

        #pragma unroll
        for (int k = 0; k < 4; k++) {
            uint32_t wC = (xl[k] > xh[k]) ? 1u : 0u;   // d=0, no shuffle
            uint32_t wL = 0u;
            #pragma unroll
            for (int s = 1; s <= 16; s++) {
                float rl = __shfl_sync(0xFFFFFFFFu, xl[k], lane + s);  // mod 32
                float rh = __shfl_sync(0xFFFFFFFFu, xh[k], lane + s);
                if (xl[k] > rl) wL |= (1u << (s - 1));     // lo pair (a, a+s)
                if (xh[k] > rh) wL |= (1u << (15 + s));    // hi pair (32+a, 32+a+s)
                if (xl[k] > rh) wC |= (1u << s);           // cross1 (a, 32+a+s)
                if (s < 16) {
                    if (xh[k] > rl) wC |= (1u << (16 + s)); // cross2 (a+s, 32+a) rev
                }
            }
            if (lane >= 16) wL &= 0x7FFF7FFFu;   // kill s=16 duplicate pairs
            int col = (warp << 2) + k;
            bits[lane][col]      = wC;
            bits[32 + lane][col] = wL;
        }
    }
    __syncthreads();

    // Gram: 136 tiles x 4 interleaved word-sets = 544 tasks, one per thread.
    // Quad lanes read rows w..w+3 (disjoint bank spans); same-(row,col) loads
    // across quads broadcast -> conflict-free crossbar traffic.
    {
        uint32_t ij = lut[tid >> 2];
        int i0 = (int)(ij >> 8), j0 = (int)(ij & 255);
        int r = tid & 3;

        int acc[16];
        #pragma unroll
        for (int k = 0; k < 16; k++) acc[k] = 0;
        #pragma unroll
        for (int step = 0; step < 16; step++) {
            int w = r + (step << 2);
            uint4 bi = *(const uint4*)&bits[w][i0];
            uint4 bj = *(const uint4*)&bits[w][j0];
            uint32_t iv[4] = {bi.x, bi.y, bi.z, bi.w};
            uint32_t jv[4] = {bj.x, bj.y, bj.z, bj.w};
            #pragma unroll
            for (int ii = 0; ii < 4; ii++)
                #pragma unroll
                for (int jj = 0; jj < 4; jj++)
                    acc[ii * 4 + jj] += __popc(iv[ii] ^ jv[jj]);
        }
        #pragma unroll
        for (int k = 0; k < 16; k++) {
            acc[k] += __shfl_xor_sync(0xFFFFFFFFu, acc[k], 1);
            acc[k] += __shfl_xor_sync(0xFFFFFFFFu, acc[k], 2);
        }
        if (r == 0) {
            #pragma unroll
            for (int k = 0; k < 16; k++) {
                int i = i0 + (k >> 2), j = j0 + (k & 3);
                if (i < j) atomicAdd(&g_H[i * NN + j], acc[k]);  // fire-and-forget
            }
        }
    }
}

// ---------------- distance + broadcast + self-clean ---------------------------
// D[i,j] = 1 - (1032192 - 4H)/2016 (2K - 4H with K = 516096), diag 0.
// After reading H, each block zeroes a distinct slice for the next graph replay.
__global__ __launch_bounds__(256) void phase3(float* __restrict__ out) {
    __shared__ __align__(16) int Hs[NN * NN];   // 16 KB
    int tid = threadIdx.x;
    int cp = blockIdx.x >> 2, q = blockIdx.x & 3;

    cudaGridDependencySynchronize();            // PDL: wait for fusedKD's REDs

    {
        const int4* s = (const int4*)g_H;
        int4* d = (int4*)Hs;
        for (int k = tid; k < 1024; k += 256) d[k] = __ldg(&s[k]);
    }
    __syncthreads();

    // Self-clean: block b zeroes int4 slice [4b, 4b+4) -> 256 blocks cover 4096 ints.
    if (tid < 4) ((int4*)g_H)[blockIdx.x * 4 + tid] = make_int4(0, 0, 0, 0);

    int base = (q << 10) + (tid << 2);          // 4 contiguous cells, same row
    int i = base >> 6, j0 = base & 63;
    float v[4];
    #pragma unroll
    for (int u = 0; u < 4; u++) {
        int j = j0 + u;
        float d = 0.0f;
        if (i != j) {
            int h = (i < j) ? Hs[i * NN + j] : Hs[j * NN + i];
            d = 1.0f - (1032192.0f - 4.0f * (float)h) * (1.0f / 2016.0f);
        }
        v[u] = d;
    }
    *(float4*)(out + (size_t)cp * (NN * NN) + base) = make_float4(v[0], v[1], v[2], v[3]);
}

extern "C" void kernel_launch(void* const* d_in, const int* in_sizes, int n_in,
                              void* d_out, int out_size) {
    (void)in_sizes; (void)n_in; (void)out_size;
    const float4* in4 = (const float4*)d_in[0];
    float* out = (float*)d_out;

    fusedKD<<<TT, NTHR>>>(in4);

    // phase3 with programmatic dependent launch (prologue overlaps fusedKD tail);
    // plain launch fallback if the attribute is rejected under capture.
    cudaLaunchAttribute at[1];
    at[0].id = cudaLaunchAttributeProgrammaticStreamSerialization;
    at[0].val.programmaticStreamSerializationAllowed = 1;
    cudaLaunchConfig_t cfg = {};
    cfg.gridDim = dim3(TT); cfg.blockDim = dim3(256);
    cfg.attrs = at; cfg.numAttrs = 1; cfg.stream = 0;
    if (cudaLaunchKernelEx(&cfg, phase3, out) != cudaSuccess)
        phase3<<<TT, 256>>>(out);
}